// round 3
// baseline (speedup 1.0000x reference)
#include <cuda_runtime.h>
#include <cstdint>

#define B_  32
#define S_  2048
#define H_  512
#define E_  1024

// Scratch (no allocations allowed in kernel_launch)
__device__ float g_dp[B_ * H_];          // dec_proj + bias, [b][h]
__device__ float g_part[4][B_][S_];      // partial logits per h-chunk

__device__ __forceinline__ float f2tf32(float x) {
    uint32_t o;
    asm("cvt.rna.tf32.f32 %0, %1;" : "=r"(o) : "f"(x));
    return __uint_as_float(o);
}

// ---------------------------------------------------------------------------
// Kernel 1: dec_proj[b,h] = decoder_hide[b,:] @ W_h[:,h] + b_attn[h]   (fp32)
// ---------------------------------------------------------------------------
__global__ __launch_bounds__(512) void dec_proj_kernel(const float* __restrict__ dh,
                                                       const float* __restrict__ W,
                                                       const float* __restrict__ bias) {
    __shared__ float dhs[H_];
    const int b = blockIdx.x;
    const int h = threadIdx.x;
    dhs[h] = dh[b * H_ + h];
    __syncthreads();
    float acc = bias[h];
#pragma unroll 8
    for (int e = 0; e < H_; e++)
        acc = fmaf(dhs[e], W[e * H_ + h], acc);   // W_h = W_attn rows [0,512)
    g_dp[b * H_ + h] = acc;
}

// ---------------------------------------------------------------------------
// Kernel 2: fused enc_proj GEMM (tf32 mma) + tanh + v_w dot -> partial logits
// CTA tile: M=128 (s), N=128 (h chunk), K=1024 in chunks of 32.
// 8 warps: 4 along M (32 rows each) x 2 along N (64 cols each).
// ---------------------------------------------------------------------------
__global__ __launch_bounds__(256) void attn_main_kernel(const float* __restrict__ enc,
                                                        const float* __restrict__ W,
                                                        const float* __restrict__ vw) {
    const int stile = blockIdx.x;   // 0..15
    const int nch   = blockIdx.y;   // 0..3
    const int b     = blockIdx.z;   // 0..31
    const int s0 = stile * 128;
    const int n0 = nch * 128;

    __shared__ float xs[128][36];       // x tile, padded stride 36 (conflict-free A frags)
    __shared__ float ws[32][132];       // W_e tile, padded stride 132
    __shared__ float dps[128];
    __shared__ float vws[128];
    __shared__ float part2[128][2];

    const int tid  = threadIdx.x;
    const int lane = tid & 31;
    const int warp = tid >> 5;
    const int wm = warp & 3;            // M strip: rows [wm*32, wm*32+32)
    const int wn = warp >> 2;           // N strip: cols [wn*64, wn*64+64)

    if (tid < 128) {
        dps[tid] = g_dp[b * H_ + n0 + tid];
        vws[tid] = vw[n0 + tid];
    }

    float d[2][8][4];
#pragma unroll
    for (int i = 0; i < 2; i++)
#pragma unroll
        for (int j = 0; j < 8; j++)
#pragma unroll
            for (int q = 0; q < 4; q++) d[i][j][q] = 0.f;

    const float* encb = enc + ((long)b * S_ + s0) * E_;
    const float* Wb   = W + (long)H_ * H_ + n0;   // W_e = W_attn rows [512,1536), col offset n0

    for (int kc = 0; kc < 32; kc++) {
        const int e0 = kc * 32;
        __syncthreads();   // previous chunk's consumers done
        // Load x tile: 128 rows x 32 cols, float4 vectorized, tf32-round once.
#pragma unroll
        for (int it = 0; it < 4; it++) {
            int idx = tid + it * 256;
            int row = idx >> 3, c4 = (idx & 7) * 4;
            float4 v = *(const float4*)(encb + (long)row * E_ + e0 + c4);
            xs[row][c4 + 0] = f2tf32(v.x);
            xs[row][c4 + 1] = f2tf32(v.y);
            xs[row][c4 + 2] = f2tf32(v.z);
            xs[row][c4 + 3] = f2tf32(v.w);
        }
        // Load W_e tile: 32 rows x 128 cols.
#pragma unroll
        for (int it = 0; it < 4; it++) {
            int idx = tid + it * 256;
            int row = idx >> 5, c4 = (idx & 31) * 4;
            float4 v = *(const float4*)(Wb + (long)(e0 + row) * H_ + c4);
            ws[row][c4 + 0] = f2tf32(v.x);
            ws[row][c4 + 1] = f2tf32(v.y);
            ws[row][c4 + 2] = f2tf32(v.z);
            ws[row][c4 + 3] = f2tf32(v.w);
        }
        __syncthreads();

#pragma unroll
        for (int ks = 0; ks < 4; ks++) {
            const int kb = ks * 8;
            uint32_t Af[2][4];
            uint32_t Bf[8][2];
#pragma unroll
            for (int mt = 0; mt < 2; mt++) {
                int r = wm * 32 + mt * 16 + (lane >> 2);
                int c = kb + (lane & 3);
                Af[mt][0] = __float_as_uint(xs[r    ][c    ]);
                Af[mt][1] = __float_as_uint(xs[r + 8][c    ]);
                Af[mt][2] = __float_as_uint(xs[r    ][c + 4]);
                Af[mt][3] = __float_as_uint(xs[r + 8][c + 4]);
            }
#pragma unroll
            for (int nt = 0; nt < 8; nt++) {
                int ncol = wn * 64 + nt * 8 + (lane >> 2);
                Bf[nt][0] = __float_as_uint(ws[kb +     (lane & 3)][ncol]);
                Bf[nt][1] = __float_as_uint(ws[kb + 4 + (lane & 3)][ncol]);
            }
#pragma unroll
            for (int mt = 0; mt < 2; mt++)
#pragma unroll
                for (int nt = 0; nt < 8; nt++)
                    asm volatile(
                        "mma.sync.aligned.m16n8k8.row.col.f32.tf32.tf32.f32 "
                        "{%0,%1,%2,%3}, {%4,%5,%6,%7}, {%8,%9}, {%0,%1,%2,%3};"
                        : "+f"(d[mt][nt][0]), "+f"(d[mt][nt][1]),
                          "+f"(d[mt][nt][2]), "+f"(d[mt][nt][3])
                        : "r"(Af[mt][0]), "r"(Af[mt][1]), "r"(Af[mt][2]), "r"(Af[mt][3]),
                          "r"(Bf[nt][0]), "r"(Bf[nt][1]));
        }
    }

    // Epilogue: energy = tanh(acc + dec_proj); partial = sum_h v_w[h] * energy
    // C frag layout: c0,c1 at row=lane>>2, cols (lane&3)*2+{0,1}; c2,c3 at row+8.
    float rs[2][2] = {{0.f, 0.f}, {0.f, 0.f}};
#pragma unroll
    for (int mt = 0; mt < 2; mt++)
#pragma unroll
        for (int nt = 0; nt < 8; nt++)
#pragma unroll
            for (int q = 0; q < 4; q++) {
                int col = wn * 64 + nt * 8 + (lane & 3) * 2 + (q & 1);
                float e = tanhf(d[mt][nt][q] + dps[col]) * vws[col];
                rs[mt][q >> 1] += e;
            }
    // Reduce across the 4 lanes sharing each row (lane&3)
#pragma unroll
    for (int mt = 0; mt < 2; mt++)
#pragma unroll
        for (int rr = 0; rr < 2; rr++) {
            float v = rs[mt][rr];
            v += __shfl_xor_sync(0xffffffffu, v, 1);
            v += __shfl_xor_sync(0xffffffffu, v, 2);
            rs[mt][rr] = v;
        }
    if ((lane & 3) == 0) {
        int g = lane >> 2;
#pragma unroll
        for (int mt = 0; mt < 2; mt++)
#pragma unroll
            for (int rr = 0; rr < 2; rr++) {
                int row = wm * 32 + mt * 16 + rr * 8 + g;
                part2[row][wn] = rs[mt][rr];
            }
    }
    __syncthreads();
    if (tid < 128)
        g_part[nch][b][s0 + tid] = part2[tid][0] + part2[tid][1];
}

// ---------------------------------------------------------------------------
// Kernel 3: sum n-chunk partials, mask, softmax over S
// ---------------------------------------------------------------------------
__global__ __launch_bounds__(256) void softmax_kernel(const int* __restrict__ mask,
                                                      float* __restrict__ out) {
    const int b = blockIdx.x;
    const int tid = threadIdx.x;
    __shared__ float red[8];
    float v[8];
#pragma unroll
    for (int i = 0; i < 8; i++) {
        int s = tid + i * 256;
        float x = g_part[0][b][s] + g_part[1][b][s] + g_part[2][b][s] + g_part[3][b][s];
        if (mask[b * S_ + s] == 0) x = -100000.0f;
        v[i] = x;
    }
    // max
    float m = v[0];
#pragma unroll
    for (int i = 1; i < 8; i++) m = fmaxf(m, v[i]);
#pragma unroll
    for (int o = 16; o > 0; o >>= 1) m = fmaxf(m, __shfl_xor_sync(0xffffffffu, m, o));
    if ((tid & 31) == 0) red[tid >> 5] = m;
    __syncthreads();
    m = red[0];
#pragma unroll
    for (int i = 1; i < 8; i++) m = fmaxf(m, red[i]);
    __syncthreads();
    // sum of exp
    float sum = 0.f;
#pragma unroll
    for (int i = 0; i < 8; i++) { v[i] = expf(v[i] - m); sum += v[i]; }
#pragma unroll
    for (int o = 16; o > 0; o >>= 1) sum += __shfl_xor_sync(0xffffffffu, sum, o);
    if ((tid & 31) == 0) red[tid >> 5] = sum;
    __syncthreads();
    sum = 0.f;
#pragma unroll
    for (int i = 0; i < 8; i++) sum += red[i];
    float inv = 1.f / sum;
#pragma unroll
    for (int i = 0; i < 8; i++) out[b * S_ + tid + i * 256] = v[i] * inv;
}

// ---------------------------------------------------------------------------
extern "C" void kernel_launch(void* const* d_in, const int* in_sizes, int n_in,
                              void* d_out, int out_size) {
    const float* dh   = (const float*)d_in[0];   // decoder_hide (32,512)
    const float* enc  = (const float*)d_in[1];   // encoder_out (32,2048,1024)
    const int*   mask = (const int*)  d_in[2];   // mask (32,2048)
    const float* W    = (const float*)d_in[3];   // W_attn (1536,512)
    const float* bias = (const float*)d_in[4];   // b_attn (512,)
    const float* vw   = (const float*)d_in[5];   // v_w (512,)
    float* out = (float*)d_out;                  // (32,2048)

    dec_proj_kernel<<<B_, H_>>>(dh, W, bias);
    attn_main_kernel<<<dim3(16, 4, B_), 256>>>(enc, W, vw);
    softmax_kernel<<<B_, 256>>>(mask, out);
}

// round 9
// speedup vs baseline: 2.4612x; 2.4612x over previous
#include <cuda_runtime.h>
#include <cuda_fp16.h>
#include <cstdint>

#define B_  32
#define S_  2048
#define H_  512
#define E_  1024

#define KCH      64                 // K per chunk (64 fp16 = 128B rows)
#define NCHUNKS  (E_ / KCH)         // 16
#define XROWSTR  72                 // smem row stride in halves (144B, 16B-aligned, ldmatrix conflict-free)

// ---------------- device scratch (no allocations allowed) -------------------
__device__ __half g_Wth[H_ * E_];   // W_e^T as fp16: [h][e], K-major for B operand
__device__ float  g_dp8[8][B_][H_]; // dec_proj partials
__device__ float  g_part[4][B_][S_];// partial logits per h-chunk

// ---------------- helpers ---------------------------------------------------
__device__ __forceinline__ float fast_tanh(float x) {
    float e = __expf(2.f * x);
    return 1.f - __fdividef(2.f, e + 1.f);
}
__device__ __forceinline__ uint32_t smem_u32(const void* p) {
    uint32_t a;
    asm("{ .reg .u64 t; cvta.to.shared.u64 t, %1; cvt.u32.u64 %0, t; }" : "=r"(a) : "l"(p));
    return a;
}
__device__ __forceinline__ void cp16h(uint32_t sa, const __half* gp) {
    asm volatile("cp.async.cg.shared.global [%0], [%1], 16;"
                 :: "r"(sa), "l"(__cvta_generic_to_global((const void*)gp)) : "memory");
}
#define CP_COMMIT() asm volatile("cp.async.commit_group;" ::: "memory")

// ---------------- SMEM layout (dynamic, bytes) -------------------------------
#define SM_XS0   0                        // 128 x 144B = 18432
#define SM_XS1   18432
#define SM_WT0   36864                    // 128 x 144B
#define SM_WT1   55296
#define SM_DPS   73728                    // 128 f32
#define SM_VWS   74240                    // 128 f32
#define SM_PART  74752                    // 128*2 f32
#define SM_TOTAL 75776

// ---------------------------------------------------------------------------
// Kernel A: W_e transpose + fp16 round:  g_Wth[h][e] = half(W_attn[512+e][h])
// ---------------------------------------------------------------------------
__global__ __launch_bounds__(256) void transpose_W(const float* __restrict__ W) {
    __shared__ float t[32][33];
    const int h0 = blockIdx.x * 32, e0 = blockIdx.y * 32;
    const int tx = threadIdx.x, ty = threadIdx.y;
#pragma unroll
    for (int i = 0; i < 4; i++)
        t[ty + i * 8][tx] = W[(long)(H_ + e0 + ty + i * 8) * H_ + h0 + tx];
    __syncthreads();
#pragma unroll
    for (int i = 0; i < 4; i++)
        g_Wth[(long)(h0 + ty + i * 8) * E_ + e0 + tx] = __float2half_rn(t[tx][ty + i * 8]);
}

// ---------------------------------------------------------------------------
// Kernel B: dec_proj partials, 8-way split over e  (fp32, full precision)
// ---------------------------------------------------------------------------
__global__ __launch_bounds__(512) void dec_proj8(const float* __restrict__ dh,
                                                 const float* __restrict__ W,
                                                 const float* __restrict__ bias) {
    __shared__ float dhs[64];
    const int b = blockIdx.x, q = blockIdx.y, h = threadIdx.x;
    const int e0 = q * 64;
    if (h < 64) dhs[h] = dh[b * H_ + e0 + h];
    __syncthreads();
    float acc = (q == 0) ? bias[h] : 0.f;
#pragma unroll 16
    for (int e = 0; e < 64; e++)
        acc = fmaf(dhs[e], W[(long)(e0 + e) * H_ + h], acc);
    g_dp8[q][b][h] = acc;
}

// ---------------------------------------------------------------------------
// Kernel C: fp16 HMMA main — 128(s) x 128(h) tile, K=1024, fused epilogue
// 8 warps: 4 along M (32 rows) x 2 along N (64 cols). m16n8k16.
// grid = (nch=4, stile=16, b=32): nch fastest so X tiles hit L2 across nch CTAs.
// ---------------------------------------------------------------------------
__global__ void __launch_bounds__(256) attn_main(const float* __restrict__ enc,
                                                 const float* __restrict__ vw) {
    extern __shared__ char smem[];
    const int tid = threadIdx.x, warp = tid >> 5, lane = tid & 31;
    const int nch = blockIdx.x, stile = blockIdx.y, b = blockIdx.z;
    const int s0 = stile * 128, n0 = nch * 128;
    const int wm = warp & 3, wn = warp >> 2;

    const uint32_t sb = smem_u32(smem);
    const uint32_t xs_a[2] = { sb + SM_XS0, sb + SM_XS1 };
    const uint32_t wt_a[2] = { sb + SM_WT0, sb + SM_WT1 };
    float* dps  = (float*)(smem + SM_DPS);
    float* vws  = (float*)(smem + SM_VWS);
    float* part = (float*)(smem + SM_PART);

    if (tid < 128) {
        float a = 0.f;
#pragma unroll
        for (int q = 0; q < 8; q++) a += g_dp8[q][b][n0 + tid];
        dps[tid] = a;
        vws[tid] = vw[n0 + tid];
    }

    float d[2][8][4];
#pragma unroll
    for (int i = 0; i < 2; i++)
#pragma unroll
        for (int j = 0; j < 8; j++)
#pragma unroll
            for (int q = 0; q < 4; q++) d[i][j][q] = 0.f;

    const float*  encb = enc + ((long)b * S_ + s0) * E_;
    const __half* wtb  = g_Wth + (long)n0 * E_;

    float4 xp[8];   // X prefetch registers (one chunk: 8 float4/thread)

    auto ldw = [&](int kc, int bufi) {
        const int e0 = kc * KCH;
#pragma unroll
        for (int i = 0; i < 4; i++) {
            int g = tid + i * 256;
            int row = g >> 3, c = g & 7;
            cp16h(wt_a[bufi] + row * 144 + c * 16, wtb + (long)row * E_ + e0 + c * 8);
        }
    };
    auto ldx = [&](int kc) {
        const int e0 = kc * KCH;
#pragma unroll
        for (int i = 0; i < 8; i++) {
            int g = tid + i * 256;
            int row = g >> 4, c4 = (g & 15) * 4;
            xp[i] = *(const float4*)(encb + (long)row * E_ + e0 + c4);
        }
    };
    auto stx = [&](int bufi) {
#pragma unroll
        for (int i = 0; i < 8; i++) {
            int g = tid + i * 256;
            int row = g >> 4, c4 = (g & 15) * 4;
            __half2 h0 = __floats2half2_rn(xp[i].x, xp[i].y);
            __half2 h1 = __floats2half2_rn(xp[i].z, xp[i].w);
            uint32_t u0 = *(uint32_t*)&h0, u1 = *(uint32_t*)&h1;
            asm volatile("st.shared.v2.b32 [%0], {%1,%2};"
                         :: "r"(xs_a[bufi] + row * 144 + c4 * 2), "r"(u0), "r"(u1) : "memory");
        }
    };

    // prologue
    ldw(0, 0); CP_COMMIT();
    ldx(0);

    for (int kc = 0; kc < NCHUNKS; kc++) {
        const int bufi = kc & 1;
        if (kc < NCHUNKS - 1) { ldw(kc + 1, bufi ^ 1); CP_COMMIT(); }
        stx(bufi);                       // X(kc) regs -> smem
        if (kc < NCHUNKS - 1) ldx(kc + 1);  // prefetch next X into regs (hidden by MMA)
        if (kc < NCHUNKS - 1) asm volatile("cp.async.wait_group 1;" ::: "memory");
        else                  asm volatile("cp.async.wait_group 0;" ::: "memory");
        __syncthreads();

#pragma unroll
        for (int ks = 0; ks < 4; ks++) {
            const int kb = ks * 16;
            uint32_t Af[2][4], Bf[4][4];
#pragma unroll
            for (int mt = 0; mt < 2; mt++) {
                int arow = wm * 32 + mt * 16 + ((lane >> 3) & 1) * 8 + (lane & 7);
                int akh  = (lane >> 4) & 1;
                uint32_t aaddr = xs_a[bufi] + arow * 144 + (kb + akh * 8) * 2;
                asm volatile("ldmatrix.sync.aligned.m8n8.x4.shared.b16 {%0,%1,%2,%3}, [%4];"
                             : "=r"(Af[mt][0]), "=r"(Af[mt][1]),
                               "=r"(Af[mt][2]), "=r"(Af[mt][3]) : "r"(aaddr));
            }
#pragma unroll
            for (int nt2 = 0; nt2 < 4; nt2++) {
                int nr  = wn * 64 + nt2 * 16 + ((lane >> 4) & 1) * 8 + (lane & 7);
                int bkh = (lane >> 3) & 1;
                uint32_t baddr = wt_a[bufi] + nr * 144 + (kb + bkh * 8) * 2;
                asm volatile("ldmatrix.sync.aligned.m8n8.x4.shared.b16 {%0,%1,%2,%3}, [%4];"
                             : "=r"(Bf[nt2][0]), "=r"(Bf[nt2][1]),
                               "=r"(Bf[nt2][2]), "=r"(Bf[nt2][3]) : "r"(baddr));
            }
#pragma unroll
            for (int mt = 0; mt < 2; mt++)
#pragma unroll
                for (int nt = 0; nt < 8; nt++) {
                    uint32_t b0 = Bf[nt >> 1][(nt & 1) * 2 + 0];
                    uint32_t b1 = Bf[nt >> 1][(nt & 1) * 2 + 1];
                    asm volatile(
                        "mma.sync.aligned.m16n8k16.row.col.f32.f16.f16.f32 "
                        "{%0,%1,%2,%3}, {%4,%5,%6,%7}, {%8,%9}, {%0,%1,%2,%3};"
                        : "+f"(d[mt][nt][0]), "+f"(d[mt][nt][1]),
                          "+f"(d[mt][nt][2]), "+f"(d[mt][nt][3])
                        : "r"(Af[mt][0]), "r"(Af[mt][1]), "r"(Af[mt][2]), "r"(Af[mt][3]),
                          "r"(b0), "r"(b1));
                }
        }
        __syncthreads();
    }

    // Epilogue: energy = tanh(acc + dec_proj); partial = sum_h v_w[h] * energy
    float rs[2][2] = {{0.f, 0.f}, {0.f, 0.f}};
#pragma unroll
    for (int mt = 0; mt < 2; mt++)
#pragma unroll
        for (int nt = 0; nt < 8; nt++)
#pragma unroll
            for (int q = 0; q < 4; q++) {
                int col = wn * 64 + nt * 8 + (lane & 3) * 2 + (q & 1);
                rs[mt][q >> 1] += fast_tanh(d[mt][nt][q] + dps[col]) * vws[col];
            }
#pragma unroll
    for (int mt = 0; mt < 2; mt++)
#pragma unroll
        for (int rr = 0; rr < 2; rr++) {
            float v = rs[mt][rr];
            v += __shfl_xor_sync(0xffffffffu, v, 1);
            v += __shfl_xor_sync(0xffffffffu, v, 2);
            rs[mt][rr] = v;
        }
    if ((lane & 3) == 0) {
        int g = lane >> 2;
#pragma unroll
        for (int mt = 0; mt < 2; mt++)
#pragma unroll
            for (int rr = 0; rr < 2; rr++)
                part[(wm * 32 + mt * 16 + rr * 8 + g) * 2 + wn] = rs[mt][rr];
    }
    __syncthreads();
    if (tid < 128)
        g_part[nch][b][s0 + tid] = part[tid * 2 + 0] + part[tid * 2 + 1];
}

// ---------------------------------------------------------------------------
// Kernel D: sum n-chunk partials, mask, softmax over S
// ---------------------------------------------------------------------------
__global__ __launch_bounds__(256) void softmax_kernel(const int* __restrict__ mask,
                                                      float* __restrict__ out) {
    const int b = blockIdx.x;
    const int tid = threadIdx.x;
    __shared__ float red[8];
    float v[8];
#pragma unroll
    for (int i = 0; i < 8; i++) {
        int s = tid + i * 256;
        float x = g_part[0][b][s] + g_part[1][b][s] + g_part[2][b][s] + g_part[3][b][s];
        if (mask[b * S_ + s] == 0) x = -100000.0f;
        v[i] = x;
    }
    float m = v[0];
#pragma unroll
    for (int i = 1; i < 8; i++) m = fmaxf(m, v[i]);
#pragma unroll
    for (int o = 16; o > 0; o >>= 1) m = fmaxf(m, __shfl_xor_sync(0xffffffffu, m, o));
    if ((tid & 31) == 0) red[tid >> 5] = m;
    __syncthreads();
    m = red[0];
#pragma unroll
    for (int i = 1; i < 8; i++) m = fmaxf(m, red[i]);
    __syncthreads();
    float sum = 0.f;
#pragma unroll
    for (int i = 0; i < 8; i++) { v[i] = expf(v[i] - m); sum += v[i]; }
#pragma unroll
    for (int o = 16; o > 0; o >>= 1) sum += __shfl_xor_sync(0xffffffffu, sum, o);
    if ((tid & 31) == 0) red[tid >> 5] = sum;
    __syncthreads();
    sum = 0.f;
#pragma unroll
    for (int i = 0; i < 8; i++) sum += red[i];
    const float inv = 1.f / sum;
#pragma unroll
    for (int i = 0; i < 8; i++) out[b * S_ + tid + i * 256] = v[i] * inv;
}

// ---------------------------------------------------------------------------
extern "C" void kernel_launch(void* const* d_in, const int* in_sizes, int n_in,
                              void* d_out, int out_size) {
    const float* dh   = (const float*)d_in[0];   // decoder_hide (32,512)
    const float* enc  = (const float*)d_in[1];   // encoder_out (32,2048,1024)
    const int*   mask = (const int*)  d_in[2];   // mask (32,2048)
    const float* W    = (const float*)d_in[3];   // W_attn (1536,512)
    const float* bias = (const float*)d_in[4];   // b_attn (512,)
    const float* vw   = (const float*)d_in[5];   // v_w (512,)
    float* out = (float*)d_out;                  // (32,2048)

    cudaFuncSetAttribute(attn_main, cudaFuncAttributeMaxDynamicSharedMemorySize, SM_TOTAL);

    transpose_W<<<dim3(16, 32), dim3(32, 8)>>>(W);
    dec_proj8<<<dim3(32, 8), 512>>>(dh, W, bias);
    attn_main<<<dim3(4, 16, 32), 256, SM_TOTAL>>>(enc, vw);
    softmax_kernel<<<B_, 256>>>(mask, out);
}